// round 14
// baseline (speedup 1.0000x reference)
#include <cuda_runtime.h>

#define BATCH 8
#define CH 3
#define H 1024
#define W 1280
#define HW (H * W)
#define EPS 1e-7f
#define MIN_DEPTH 10.0f
#define MAX_DEPTH 255.0f

#define TILE_W 128
#define TILE_H 8
#define RPT 4                 // rows per thread

// Phase-batched body; single-division projection (grid scales prefolded).
// Phase 3 uses tap-major (miss-first) ordering.
template <bool INTERIOR>
__device__ __forceinline__ void synth_body(const float* __restrict__ img,
                                           const float* __restrict__ disp,
                                           float* __restrict__ out,
                                           const float* sP,
                                           int b, int yt, int xt, int tid) {
    const float m1 = sP[1], m4 = sP[4], m7 = sP[7];
    const float c0 = sP[9], c1 = sP[10], c2e = sP[11];

    const int lx = tid & (TILE_W - 1);   // adjacent lanes -> adjacent x
    const int rp = tid >> 7;             // 0 or 1
    const int x  = xt + lx;
    const float fx = (float)x;

    const float tx_x = sP[0] * fx + sP[2];
    const float tx_y = sP[3] * fx + sP[5];
    const float tx_z = sP[6] * fx + sP[8];

    const float min_disp = 1.0f / MAX_DEPTH;
    const float drange   = 1.0f / MIN_DEPTH - 1.0f / MAX_DEPTH;

    const float* dbase = disp + (size_t)b * HW;
    const float* imb   = img  + (size_t)b * CH * HW;
    float* outb        = out  + (size_t)b * CH * HW;

    const int gidx0 = (yt + rp) * W + x;

    // ---- Phase 1: all disp loads (independent, overlapped) ----
    float dval[RPT];
#pragma unroll
    for (int k = 0; k < RPT; k++)
        dval[k] = __ldg(dbase + gidx0 + k * 2 * W);

    // ---- Phase 2: all coordinates / weights / tap offsets ----
    int   o00[RPT], odx[RPT], ody[RPT];
    float w00[RPT], w01[RPT], w10[RPT], w11[RPT];
    const float fy0 = (float)(yt + rp);
    float ay_x = m1 * fy0 + tx_x;  const float sy_x = 2.0f * m1;
    float ay_y = m4 * fy0 + tx_y;  const float sy_y = 2.0f * m4;
    float ay_z = m7 * fy0 + tx_z;  const float sy_z = 2.0f * m7;

#pragma unroll
    for (int k = 0; k < RPT; k++) {
        float s  = fmaf(drange, dval[k], min_disp);     // 1/depth
        float nx = fmaf(c0,  s, ay_x);
        float ny = fmaf(c1,  s, ay_y);
        float dz = fmaf(c2e, s, ay_z);
        ay_x += sy_x; ay_y += sy_y; ay_z += sy_z;

        float rz = __fdividef(1.0f, dz);                // the ONLY division
        float xf = fmaf(nx, rz, -0.5f);
        float yf = fmaf(ny, rz, -0.5f);

        int ix0 = __float2int_rd(xf);
        int iy0 = __float2int_rd(yf);
        float wx = xf - (float)ix0;
        float wy = yf - (float)iy0;

        if (INTERIOR) {
            o00[k] = iy0 * W + ix0;
            odx[k] = 1;
            ody[k] = W;
        } else {
            int ix1 = min(max(ix0 + 1, 0), W - 1);
            int iy1 = min(max(iy0 + 1, 0), H - 1);
            ix0 = min(max(ix0, 0), W - 1);
            iy0 = min(max(iy0, 0), H - 1);
            o00[k] = iy0 * W + ix0;
            odx[k] = ix1 - ix0;
            ody[k] = (iy1 - iy0) * W;
        }

        float iwx = 1.0f - wx;
        float iwy = 1.0f - wy;
        w00[k] = iwx * iwy;
        w01[k] = wx * iwy;
        w10[k] = iwx * wy;
        w11[k] = wx * wy;
    }

    // ---- Phase 3: tap-major (miss-first) gathers ----
    float t00[RPT][CH], t01[RPT][CH], t10[RPT][CH], t11[RPT][CH];
#pragma unroll
    for (int k = 0; k < RPT; k++) {
        const float* p00 = imb + o00[k];
#pragma unroll
        for (int ch = 0; ch < CH; ch++)
            t00[k][ch] = __ldg(p00 + ch * HW);
    }
#pragma unroll
    for (int k = 0; k < RPT; k++) {
        const float* p10 = imb + o00[k] + ody[k];
#pragma unroll
        for (int ch = 0; ch < CH; ch++)
            t10[k][ch] = __ldg(p10 + ch * HW);
    }
#pragma unroll
    for (int k = 0; k < RPT; k++) {
        const float* p01 = imb + o00[k] + odx[k];
#pragma unroll
        for (int ch = 0; ch < CH; ch++)
            t01[k][ch] = __ldg(p01 + ch * HW);
    }
#pragma unroll
    for (int k = 0; k < RPT; k++) {
        const float* p11 = imb + o00[k] + ody[k] + odx[k];
#pragma unroll
        for (int ch = 0; ch < CH; ch++)
            t11[k][ch] = __ldg(p11 + ch * HW);
    }

    // ---- Phase 4: blend + store ----
#pragma unroll
    for (int k = 0; k < RPT; k++) {
        const int gidx = gidx0 + k * 2 * W;
#pragma unroll
        for (int ch = 0; ch < CH; ch++) {
            float v = t00[k][ch] * w00[k];
            v = fmaf(t01[k][ch], w01[k], v);
            v = fmaf(t10[k][ch], w10[k], v);
            v = fmaf(t11[k][ch], w11[k], v);
            outb[ch * HW + gidx] = v;
        }
    }
}

// Prefetch one tile's img footprint to L2 (180 lines: 10 rows x 3 ch x 6 lines).
__device__ __forceinline__ void prefetch_tile(const float* imb, int yt, int xt, int tid) {
    if (tid < 180) {
        int ch = tid / 60;               // 0..2
        int r6 = tid - ch * 60;          // 0..59
        int r  = r6 / 6;                 // row 0..9
        int l  = r6 - r * 6;             // line 0..5
        int gy = min(max(yt - 1 + r, 0), H - 1);
        int gc = min(max(xt - 2, 0), W - 136);
        const char* base = (const char*)(imb + ch * HW + gy * W + gc);
        const char* linep = (const char*)((size_t)base & ~(size_t)127) + l * 128;
        asm volatile("prefetch.global.L2 [%0];" :: "l"(linep));
    }
}

// Double-tile pipelined kernel: block owns tiles A (bx*256) and B (bx*256+128).
// Prefetch both at entry -> tile B's gathers get full L2-fill lead time.
__global__ __launch_bounds__(256, 6) void synth_kernel(const float* __restrict__ img,
                                                       const float* __restrict__ disp,
                                                       const float* __restrict__ srcK,
                                                       const float* __restrict__ tgtK,
                                                       const float* __restrict__ tvec,
                                                       float* __restrict__ out) {
    __shared__ float sP[12];

    const int b   = blockIdx.z;
    const int yt  = blockIdx.y * TILE_H;
    const int xtA = blockIdx.x * (2 * TILE_W);
    const int xtB = xtA + TILE_W;
    const int tid = threadIdx.x;

    const float* imb = img + (size_t)b * CH * HW;

    // ---- L2 prefetch: tile A (immediate use), tile B (full lead), B's disp ----
    prefetch_tile(imb, yt, xtA, tid);
    prefetch_tile(imb, yt, xtB, tid);
    if (tid >= 192 && tid < 192 + 32) {   // B disp: 8 rows x 4 lines = 32 lines
        int i = tid - 192;
        int r = i >> 2;                   // row 0..7
        int l = i & 3;                    // line 0..3
        const char* base = (const char*)(disp + (size_t)b * HW + (yt + r) * W + xtB);
        const char* linep = (const char*)((size_t)base & ~(size_t)127) + l * 128;
        asm volatile("prefetch.global.L2 [%0];" :: "l"(linep));
    }

    if (tid < 12) {
        const float* S = srcK + b * 16;
        const float* T = tgtK + b * 16;
        const float* t = tvec + b * 3;

        float a00 = __ldg(S + 0), a01 = __ldg(S + 1), a02 = __ldg(S + 2);
        float a10 = __ldg(S + 4), a11 = __ldg(S + 5), a12 = __ldg(S + 6);
        float a20 = __ldg(S + 8), a21 = __ldg(S + 9), a22 = __ldg(S + 10);
        float ad00 = a11 * a22 - a12 * a21;
        float ad01 = a02 * a21 - a01 * a22;
        float ad02 = a01 * a12 - a02 * a11;
        float ad10 = a12 * a20 - a10 * a22;
        float ad11 = a00 * a22 - a02 * a20;
        float ad12 = a02 * a10 - a00 * a12;
        float ad20 = a10 * a21 - a11 * a20;
        float ad21 = a01 * a20 - a00 * a21;
        float ad22 = a00 * a11 - a01 * a10;
        float id = 1.0f / (a00 * ad00 + a01 * ad10 + a02 * ad20);

        int r = (tid < 9) ? (tid / 3) : (tid - 9);
        float T0 = __ldg(T + r * 4 + 0);
        float T1 = __ldg(T + r * 4 + 1);
        float T2 = __ldg(T + r * 4 + 2);

        float val;
        if (tid < 9) {
            int c = tid - r * 3;
            float A0 = (c == 0) ? ad00 : (c == 1) ? ad01 : ad02;
            float A1 = (c == 0) ? ad10 : (c == 1) ? ad11 : ad12;
            float A2 = (c == 0) ? ad20 : (c == 1) ? ad21 : ad22;
            val = (T0 * A0 + T1 * A1 + T2 * A2) * id;
        } else {
            val = T0 * __ldg(t + 0) + T1 * __ldg(t + 1) + T2 * __ldg(t + 2);
        }

        const float SXW = (float)W / (float)(W - 1);
        const float SYH = (float)H / (float)(H - 1);
        if (r == 0)        val *= SXW;
        else if (r == 1)   val *= SYH;
        else if (tid == 11) val += EPS;
        sP[tid] = val;
    }
    __syncthreads();

    const bool yInt = (blockIdx.y > 0) & (blockIdx.y < gridDim.y - 1);
    const bool intA = yInt & (blockIdx.x > 0);                 // A leftmost when bx==0
    const bool intB = yInt & (blockIdx.x < gridDim.x - 1);     // B rightmost when bx==last

    if (intA) synth_body<true >(img, disp, out, sP, b, yt, xtA, tid);
    else      synth_body<false>(img, disp, out, sP, b, yt, xtA, tid);

    if (intB) synth_body<true >(img, disp, out, sP, b, yt, xtB, tid);
    else      synth_body<false>(img, disp, out, sP, b, yt, xtB, tid);
}

extern "C" void kernel_launch(void* const* d_in, const int* in_sizes, int n_in,
                              void* d_out, int out_size) {
    const float* img  = (const float*)d_in[0];
    const float* disp = (const float*)d_in[1];
    const float* srcK = (const float*)d_in[2];
    const float* tgtK = (const float*)d_in[3];
    const float* tvec = (const float*)d_in[4];
    float* out = (float*)d_out;

    dim3 grid(W / (2 * TILE_W), H / TILE_H, BATCH);   // (5, 128, 8)
    synth_kernel<<<grid, 256>>>(img, disp, srcK, tgtK, tvec, out);
}